// round 10
// baseline (speedup 1.0000x reference)
#include <cuda_runtime.h>
#include <cuda_fp16.h>
#include <cuda_bf16.h>
#include <mma.h>
#include <cstdint>

using namespace nvcuda;

// Problem constants (fixed by the reference)
#define MAXN 50000
#define DIMV 128
#define HEADS 4
#define CH 32
#define MAXE 800000
#define LRELU_SLOPE 0.2f
#define LN_EPS 1e-5f

typedef unsigned long long ull;

// ---------------- scratch (device globals; no allocation allowed) ----------------
// g_hb layout: [N][128] words, word = 2 bf16. For channel-pair p (0..63), layer l:
//   word = (p>>1)*4 + l*2 + (p&1)
// => lane's uint4 at word lane*4 = {h1 pairs 2lane,2lane+1, h2 pairs 2lane,2lane+1}
__device__ unsigned int g_hb[MAXN * 128];
__device__ float g_srcv[MAXN * 8];          // [node][head][layer] : float2 per head
__device__ float g_dstv[MAXN * 8];          // same layout
__device__ int   g_deg[MAXN];               // edge in-degree (zero-init; self-loop via +1)
__device__ int   g_off[MAXN + 1];           // CSR offsets
__device__ int   g_cursor[MAXN];            // scatter cursors
__device__ int   g_csr[MAXE + MAXN];        // CSR src indices (grouped by dst)
__device__ int   g_bsum[256];               // per-block degree sums
__device__ int   g_boff[256];               // exclusive block offsets

__device__ __forceinline__ float lrelu(float v) { return v > 0.f ? v : LRELU_SLOPE * v; }

__device__ __forceinline__ ull pack2(float x, float y) {
    ull r;
    asm("mov.b64 %0, {%1, %2};" : "=l"(r) : "f"(x), "f"(y));
    return r;
}
__device__ __forceinline__ void unpack2(ull v, float& x, float& y) {
    asm("mov.b64 {%0, %1}, %2;" : "=f"(x), "=f"(y) : "l"(v));
}
__device__ __forceinline__ void ffma2(ull& d, ull a, ull b) {
    asm("fma.rn.f32x2 %0, %1, %2, %0;" : "+l"(d) : "l"(a), "l"(b));
}
__device__ __forceinline__ unsigned int f2bf2(float lo, float hi) {
    unsigned int r;
    asm("cvt.rn.bf16x2.f32 %0, %1, %2;" : "=r"(r) : "f"(hi), "f"(lo));
    return r;
}
// word of two bf16 -> packed f32x2 (exact: bf16->f32 is <<16)
__device__ __forceinline__ ull bf2f2(unsigned int w) {
    ull r;
    asm("mov.b64 %0, {%1, %2};" : "=l"(r) : "r"(w << 16), "r"(w & 0xffff0000u));
    return r;
}

// ---------------- kernel 1: h = x @ [W1|W2] via HMMA + fused attention logits ----------------
// grid: (ceil(n/64), 2 layers), block 256 (8 warps). Tile M=64, N=128, K=128 (2 chunks of 64).
#define XH_LD 72
#define WH_LD 136
#define CS_LD 132
#define GEMM_SMEM 33792   // max(64*72*2 + 64*136*2, 64*132*4)
__global__ __launch_bounds__(256) void gemm_hmma(const float* __restrict__ x,
                                                 const float* __restrict__ W1,
                                                 const float* __restrict__ W2,
                                                 const float* __restrict__ as1,
                                                 const float* __restrict__ ad1,
                                                 const float* __restrict__ as2,
                                                 const float* __restrict__ ad2, int n) {
    __shared__ __align__(16) char buf[GEMM_SMEM];
    half (*Xh)[XH_LD] = (half(*)[XH_LD])buf;                     // 64 x 72 half
    half (*Wh)[WH_LD] = (half(*)[WH_LD])(buf + 64 * XH_LD * 2);  // 64 x 136 half
    float (*Cs)[CS_LD] = (float(*)[CS_LD])buf;                   // 64 x 132 float (aliases)

    int tid = threadIdx.x;
    int rowBase = blockIdx.x * 64;
    int l = blockIdx.y;
    const float* W = (l == 0) ? W1 : W2;
    int warp = tid >> 5;
    int wr = warp & 3;    // 4 row groups of 16
    int wc = warp >> 2;   // 2 col groups of 64

    wmma::fragment<wmma::accumulator, 16, 16, 16, float> acc[4];
#pragma unroll
    for (int j = 0; j < 4; j++) wmma::fill_fragment(acc[j], 0.f);

    int row4 = tid >> 2, q4 = tid & 3;   // 4 threads per row of 64
    for (int k0 = 0; k0 < DIMV; k0 += 64) {
        // load X tile 64x64 (fp32 -> half): 4 threads/row, 16 cols each
        {
            int grow = rowBase + row4;
#pragma unroll
            for (int i = 0; i < 4; i++) {
                float4 v = make_float4(0.f, 0.f, 0.f, 0.f);
                if (grow < n) v = *(const float4*)&x[grow * DIMV + k0 + q4 * 16 + i * 4];
                half2* dst = (half2*)&Xh[row4][q4 * 16 + i * 4];
                dst[0] = __floats2half2_rn(v.x, v.y);
                dst[1] = __floats2half2_rn(v.z, v.w);
            }
        }
        // load W tile 64x128 (fp32 -> half): 4 threads/row, 32 cols each
        {
#pragma unroll
            for (int i = 0; i < 8; i++) {
                float4 v = *(const float4*)&W[(k0 + row4) * DIMV + q4 * 32 + i * 4];
                half2* dst = (half2*)&Wh[row4][q4 * 32 + i * 4];
                dst[0] = __floats2half2_rn(v.x, v.y);
                dst[1] = __floats2half2_rn(v.z, v.w);
            }
        }
        __syncthreads();
#pragma unroll
        for (int kk = 0; kk < 4; kk++) {
            wmma::fragment<wmma::matrix_a, 16, 16, 16, half, wmma::row_major> fa;
            wmma::load_matrix_sync(fa, &Xh[wr * 16][kk * 16], XH_LD);
#pragma unroll
            for (int j = 0; j < 4; j++) {
                wmma::fragment<wmma::matrix_b, 16, 16, 16, half, wmma::row_major> fb;
                wmma::load_matrix_sync(fb, &Wh[kk * 16][wc * 64 + j * 16], WH_LD);
                wmma::mma_sync(acc[j], fa, fb, acc[j]);
            }
        }
        __syncthreads();
    }
    // stage C through smem
#pragma unroll
    for (int j = 0; j < 4; j++)
        wmma::store_matrix_sync(&Cs[wr * 16][wc * 64 + j * 16], acc[j], CS_LD, wmma::mem_row_major);
    __syncthreads();
    {
        int grow = rowBase + row4;
        if (grow < n) {
            // 1) repack to interleaved bf16
#pragma unroll
            for (int pp = 0; pp < 16; pp += 2) {
                int p = 16 * q4 + pp;           // even channel-pair index
                float c0 = Cs[row4][2 * p + 0];
                float c1 = Cs[row4][2 * p + 1];
                float c2 = Cs[row4][2 * p + 2];
                float c3 = Cs[row4][2 * p + 3];
                uint2 w2;
                w2.x = f2bf2(c0, c1);
                w2.y = f2bf2(c2, c3);
                *(uint2*)&g_hb[grow * 128 + (p >> 1) * 4 + 2 * l] = w2;
            }
            // 2) fused attention logits: thread q4 owns head q4 (channels 32q4..32q4+31)
            const float* as = (l == 0) ? as1 : as2;
            const float* ad = (l == 0) ? ad1 : ad2;
            float ps = 0.f, pd = 0.f;
#pragma unroll
            for (int c = 0; c < 32; c += 4) {
                float4 h4 = *(const float4*)&Cs[row4][q4 * 32 + c];
                float4 a4 = *(const float4*)&as[q4 * CH + c];
                float4 d4 = *(const float4*)&ad[q4 * CH + c];
                ps += h4.x * a4.x + h4.y * a4.y + h4.z * a4.z + h4.w * a4.w;
                pd += h4.x * d4.x + h4.y * d4.y + h4.z * d4.z + h4.w * d4.w;
            }
            g_srcv[grow * 8 + q4 * 2 + l] = ps;
            g_dstv[grow * 8 + q4 * 2 + l] = pd;
        }
    }
}

// ---------------- CSR build (runs concurrently with GEMM on a side stream) ----------------
__global__ void count_kernel(const int* __restrict__ ei, int E) {
    int e4 = blockIdx.x * blockDim.x + threadIdx.x;
    int base = e4 * 4;
    if (base + 4 <= E && (E & 3) == 0) {
        int4 d = *(const int4*)&ei[E + base];
        atomicAdd(&g_deg[d.x], 1);
        atomicAdd(&g_deg[d.y], 1);
        atomicAdd(&g_deg[d.z], 1);
        atomicAdd(&g_deg[d.w], 1);
    } else {
        for (int e = base; e < E && e < base + 4; e++) atomicAdd(&g_deg[ei[E + e]], 1);
    }
}

// deg+1 semantics everywhere: self-loop included without explicit init.
__global__ __launch_bounds__(256) void scanA_kernel(int n) {
    __shared__ int sm[8];
    int t = threadIdx.x;
    int i = blockIdx.x * 256 + t;
    int v = (i < n) ? g_deg[i] + 1 : 0;
#pragma unroll
    for (int off = 16; off; off >>= 1) v += __shfl_xor_sync(0xffffffffu, v, off);
    if ((t & 31) == 0) sm[t >> 5] = v;
    __syncthreads();
    if (t == 0) {
        int s = 0;
#pragma unroll
        for (int j = 0; j < 8; j++) s += sm[j];
        g_bsum[blockIdx.x] = s;
    }
}

__global__ __launch_bounds__(256) void scanB_kernel(int nb, int n) {
    __shared__ int sm[256];
    int t = threadIdx.x;
    int v = (t < nb) ? g_bsum[t] : 0;
    sm[t] = v;
    __syncthreads();
#pragma unroll
    for (int off = 1; off < 256; off <<= 1) {
        int u = (t >= off) ? sm[t - off] : 0;
        __syncthreads();
        sm[t] += u;
        __syncthreads();
    }
    g_boff[t] = sm[t] - v;  // exclusive
    if (t == nb - 1) g_off[n] = sm[t];
}

__global__ __launch_bounds__(256) void scanC_kernel(int n) {
    __shared__ int wsum[8];
    int t = threadIdx.x;
    int lane = t & 31, w = t >> 5;
    int i = blockIdx.x * 256 + t;
    int v = (i < n) ? g_deg[i] + 1 : 0;
    int x = v;
#pragma unroll
    for (int off = 1; off < 32; off <<= 1) {
        int u = __shfl_up_sync(0xffffffffu, x, off);
        if (lane >= off) x += u;
    }
    if (lane == 31) wsum[w] = x;
    __syncthreads();
    if (t == 0) {
        int acc = 0;
#pragma unroll
        for (int j = 0; j < 8; j++) { int tmp = wsum[j]; wsum[j] = acc; acc += tmp; }
    }
    __syncthreads();
    if (i < n) {
        int base = g_boff[blockIdx.x] + wsum[w] + (x - v);   // exclusive prefix
        g_off[i] = base;
        g_csr[base] = i;          // self-loop first
        g_cursor[i] = base + 1;
        g_deg[i] = 0;             // re-zero for next replay (deterministic)
    }
}

__global__ void scatter_kernel(const int* __restrict__ ei, int E) {
    int e4 = blockIdx.x * blockDim.x + threadIdx.x;
    int base = e4 * 4;
    if (base + 4 <= E && (E & 3) == 0) {
        int4 s = *(const int4*)&ei[base];
        int4 d = *(const int4*)&ei[E + base];
        g_csr[atomicAdd(&g_cursor[d.x], 1)] = s.x;
        g_csr[atomicAdd(&g_cursor[d.y], 1)] = s.y;
        g_csr[atomicAdd(&g_cursor[d.z], 1)] = s.z;
        g_csr[atomicAdd(&g_cursor[d.w], 1)] = s.w;
    } else {
        for (int e = base; e < E && e < base + 4; e++)
            g_csr[atomicAdd(&g_cursor[ei[E + e]], 1)] = ei[e];
    }
}

// ---------------- kernel 3: CSR aggregation + gate + residual + LN (warp per node) ----------------
__global__ __launch_bounds__(256) void agg_finalize_kernel(
        const float* __restrict__ x,
        const float* __restrict__ b1, const float* __restrict__ b2,
        const float* __restrict__ gW, const float* __restrict__ gb,
        const float* __restrict__ gamma, const float* __restrict__ beta,
        float* __restrict__ out, int n) {
    int node = (blockIdx.x * blockDim.x + threadIdx.x) >> 5;
    if (node >= n) return;
    int lane = threadIdx.x & 31;
    int head = lane >> 3;
    int c0 = lane * 4;
    const unsigned FULL = 0xffffffffu;

    float2 ed = *(const float2*)&g_dstv[node * 8 + head * 2];  // (ed1, ed2)
    int beg = g_off[node];
    int end = g_off[node + 1];

    ull num1a = 0ull, num1b = 0ull, num2a = 0ull, num2b = 0ull;
    float den1 = 0.f, den2 = 0.f;

#define AGG_STEP(e, q) {                                        \
        float p1 = __expf(lrelu((e).x + ed.x));                 \
        float p2 = __expf(lrelu((e).y + ed.y));                 \
        den1 += p1; den2 += p2;                                 \
        ull pa = pack2(p1, p1), pb = pack2(p2, p2);             \
        ffma2(num1a, pa, bf2f2((q).x));                         \
        ffma2(num1b, pa, bf2f2((q).y));                         \
        ffma2(num2a, pb, bf2f2((q).z));                         \
        ffma2(num2b, pb, bf2f2((q).w));                         \
    }

    int p = beg;
    // 4-edge chunks: one coalesced csr fetch + broadcast, then 4 independent load chains
    for (; p + 4 <= end; p += 4) {
        int idx = __ldg(&g_csr[p + (lane & 3)]);
        int s0 = __shfl_sync(FULL, idx, 0, 4);
        int s1 = __shfl_sync(FULL, idx, 1, 4);
        int s2 = __shfl_sync(FULL, idx, 2, 4);
        int s3 = __shfl_sync(FULL, idx, 3, 4);
        uint4 q0 = *(const uint4*)&g_hb[s0 * 128 + lane * 4];
        uint4 q1 = *(const uint4*)&g_hb[s1 * 128 + lane * 4];
        uint4 q2 = *(const uint4*)&g_hb[s2 * 128 + lane * 4];
        uint4 q3 = *(const uint4*)&g_hb[s3 * 128 + lane * 4];
        float2 e0 = *(const float2*)&g_srcv[s0 * 8 + head * 2];
        float2 e1 = *(const float2*)&g_srcv[s1 * 8 + head * 2];
        float2 e2 = *(const float2*)&g_srcv[s2 * 8 + head * 2];
        float2 e3 = *(const float2*)&g_srcv[s3 * 8 + head * 2];
        AGG_STEP(e0, q0)
        AGG_STEP(e1, q1)
        AGG_STEP(e2, q2)
        AGG_STEP(e3, q3)
    }
    for (; p < end; p++) {
        int s = __ldg(&g_csr[p]);
        uint4 q = *(const uint4*)&g_hb[s * 128 + lane * 4];
        float2 e = *(const float2*)&g_srcv[s * 8 + head * 2];
        AGG_STEP(e, q)
    }
#undef AGG_STEP

    float inv1 = 1.f / den1;
    float inv2 = 1.f / den2;
    float4 num1, num2;
    unpack2(num1a, num1.x, num1.y); unpack2(num1b, num1.z, num1.w);
    unpack2(num2a, num2.x, num2.y); unpack2(num2b, num2.z, num2.w);
    float4 bb1 = *(const float4*)&b1[c0];
    float4 bb2 = *(const float4*)&b2[c0];
    float4 o1, o2;
    o1.x = num1.x * inv1 + bb1.x; o1.y = num1.y * inv1 + bb1.y;
    o1.z = num1.z * inv1 + bb1.z; o1.w = num1.w * inv1 + bb1.w;
    o2.x = num2.x * inv2 + bb2.x; o2.y = num2.y * inv2 + bb2.y;
    o2.z = num2.z * inv2 + bb2.z; o2.w = num2.w * inv2 + bb2.w;

    // gate logits: cat(out1,out2) @ gate_W[256,2]
    float g0 = 0.f, g1 = 0.f;
    {
        const float* w1r = &gW[c0 * 2];
        const float* w2r = &gW[(128 + c0) * 2];
        g0 += o1.x * w1r[0] + o1.y * w1r[2] + o1.z * w1r[4] + o1.w * w1r[6];
        g1 += o1.x * w1r[1] + o1.y * w1r[3] + o1.z * w1r[5] + o1.w * w1r[7];
        g0 += o2.x * w2r[0] + o2.y * w2r[2] + o2.z * w2r[4] + o2.w * w2r[6];
        g1 += o2.x * w2r[1] + o2.y * w2r[3] + o2.z * w2r[5] + o2.w * w2r[7];
    }
#pragma unroll
    for (int off = 16; off; off >>= 1) {
        g0 += __shfl_xor_sync(0xffffffffu, g0, off);
        g1 += __shfl_xor_sync(0xffffffffu, g1, off);
    }
    g0 += gb[0]; g1 += gb[1];
    float mx = fmaxf(g0, g1);
    float e0 = __expf(g0 - mx), e1 = __expf(g1 - mx);
    float inv_se = 1.f / (e0 + e1);
    float w0 = e0 * inv_se, w1 = e1 * inv_se;

    float4 xv = *(const float4*)&x[node * DIMV + c0];
    float4 y;
    y.x = xv.x + w0 * o1.x + w1 * o2.x;
    y.y = xv.y + w0 * o1.y + w1 * o2.y;
    y.z = xv.z + w0 * o1.z + w1 * o2.z;
    y.w = xv.w + w0 * o1.w + w1 * o2.w;
    float sum = y.x + y.y + y.z + y.w;
    float sq  = y.x * y.x + y.y * y.y + y.z * y.z + y.w * y.w;
#pragma unroll
    for (int off = 16; off; off >>= 1) {
        sum += __shfl_xor_sync(0xffffffffu, sum, off);
        sq  += __shfl_xor_sync(0xffffffffu, sq, off);
    }
    float mu = sum * (1.f / DIMV);
    float var = sq * (1.f / DIMV) - mu * mu;
    float inv = rsqrtf(var + LN_EPS);
    float4 gm = *(const float4*)&gamma[c0];
    float4 bt = *(const float4*)&beta[c0];
    float4 r;
    r.x = (y.x - mu) * inv * gm.x + bt.x;
    r.y = (y.y - mu) * inv * gm.y + bt.y;
    r.z = (y.z - mu) * inv * gm.z + bt.z;
    r.w = (y.w - mu) * inv * gm.w + bt.w;
    *(float4*)&out[node * DIMV + c0] = r;
}

// ---------------- stream/event infrastructure (created once at load) ----------------
static cudaStream_t g_s1;
static cudaEvent_t g_evFork, g_evJoin;
static int g_stream_init = []() {
    cudaStreamCreateWithFlags(&g_s1, cudaStreamNonBlocking);
    cudaEventCreateWithFlags(&g_evFork, cudaEventDisableTiming);
    cudaEventCreateWithFlags(&g_evJoin, cudaEventDisableTiming);
    return 0;
}();

// ---------------- launch ----------------
extern "C" void kernel_launch(void* const* d_in, const int* in_sizes, int n_in,
                              void* d_out, int out_size) {
    const float* x   = (const float*)d_in[0];
    const int*   ei  = (const int*)d_in[1];
    const float* W1  = (const float*)d_in[2];
    const float* b1  = (const float*)d_in[3];
    const float* as1 = (const float*)d_in[4];
    const float* ad1 = (const float*)d_in[5];
    const float* W2  = (const float*)d_in[6];
    const float* b2  = (const float*)d_in[7];
    const float* as2 = (const float*)d_in[8];
    const float* ad2 = (const float*)d_in[9];
    const float* gW  = (const float*)d_in[10];
    const float* gb  = (const float*)d_in[11];
    const float* gam = (const float*)d_in[12];
    const float* bet = (const float*)d_in[13];
    float* out = (float*)d_out;

    int n = in_sizes[0] / DIMV;       // nodes
    int E = in_sizes[1] / 2;          // edges (before self-loops)
    int nb = (n + 255) / 256;         // scan blocks (<= 256)
    int e4 = (E + 3) / 4;             // 4-edge work items

    // Fork: CSR build (depends only on ei) runs on side stream, concurrent with GEMM.
    cudaEventRecord(g_evFork, 0);
    cudaStreamWaitEvent(g_s1, g_evFork, 0);

    // Branch A (stream 0): h = x @ [W1|W2] via HMMA + fused logits
    gemm_hmma<<<dim3((n + 63) / 64, 2), 256>>>(x, W1, W2, as1, ad1, as2, ad2, n);

    // Branch B (stream s1): CSR build (dst-grouped)
    count_kernel<<<(e4 + 255) / 256, 256, 0, g_s1>>>(ei, E);
    scanA_kernel<<<nb, 256, 0, g_s1>>>(n);
    scanB_kernel<<<1, 256, 0, g_s1>>>(nb, n);
    scanC_kernel<<<nb, 256, 0, g_s1>>>(n);
    scatter_kernel<<<(e4 + 255) / 256, 256, 0, g_s1>>>(ei, E);

    // Join
    cudaEventRecord(g_evJoin, g_s1);
    cudaStreamWaitEvent(0, g_evJoin, 0);

    // Aggregation + gate + residual + LN
    agg_finalize_kernel<<<(n * 32 + 255) / 256, 256>>>(x, b1, b2, gW, gb, gam, bet, out, n);
}